// round 5
// baseline (speedup 1.0000x reference)
#include <cuda_runtime.h>
#include <cuda_bf16.h>
#include <cstdint>
#include <cstddef>

// ---------------- problem constants ----------------
#define HWSZ 3136          // 56*56
#define NPIX 100352        // 32*3136

// ---------------- scratch (device globals; no runtime alloc) ----------------
__device__ __align__(256) __nv_bfloat16 g_ba1a[(size_t)NPIX * 256];
__device__ __align__(256) __nv_bfloat16 g_ba1b[(size_t)NPIX * 256];
__device__ __align__(256) __nv_bfloat16 g_ba2a[(size_t)NPIX * 256];
__device__ __align__(256) __nv_bfloat16 g_ba2b[(size_t)NPIX * 256];
__device__ __align__(256) float         g_out1[(size_t)NPIX * 256];   // NCHW
__device__ __align__(256) __nv_bfloat16 g_wB[2][9 * 256 * 256];       // [tap][co][ci] signs
__device__ float g_s1[2][256];
__device__ float g_s2[2][256];
__device__ float g_c0[2][256];

// ---------------- helpers ----------------
__device__ __forceinline__ __nv_bfloat16 sgnb(float v) {
    float s = (v > 0.0f) ? 1.0f : ((v < 0.0f) ? -1.0f : 0.0f);
    return __float2bfloat16(s);
}

__device__ __forceinline__ uint32_t sw(uint32_t o) {   // SW128 swizzle
    return o ^ ((o >> 3) & 0x70);
}

__device__ __forceinline__ void cp16(uint32_t dst, const void* src, bool pred) {
    int sz = pred ? 16 : 0;
    asm volatile("cp.async.cg.shared.global [%0], [%1], 16, %2;"
                 :: "r"(dst), "l"(src), "r"(sz));
}

#define LDSM4(R0,R1,R2,R3,ADDR) \
    asm volatile("ldmatrix.sync.aligned.m8n8.x4.shared.b16 {%0,%1,%2,%3}, [%4];" \
        : "=r"(R0),"=r"(R1),"=r"(R2),"=r"(R3) : "r"(ADDR))

#define MMA_OP(D, A, B0, B1) \
    asm volatile("mma.sync.aligned.m16n8k16.row.col.f32.bf16.bf16.f32 " \
        "{%0,%1,%2,%3}, {%4,%5,%6,%7}, {%8,%9}, {%0,%1,%2,%3};" \
        : "+f"((D)[0]), "+f"((D)[1]), "+f"((D)[2]), "+f"((D)[3]) \
        : "r"((A)[0]), "r"((A)[1]), "r"((A)[2]), "r"((A)[3]), "r"(B0), "r"(B1))

// ---------------- weight prep: alpha, sign weights, folded BN constants ----------------
__global__ void wprep_kernel(int sub,
                             const float* __restrict__ w,
                             const float* __restrict__ sc,
                             const float* __restrict__ g,
                             const float* __restrict__ b,
                             const float* __restrict__ m,
                             const float* __restrict__ v) {
    int co = blockIdx.x;      // 0..255
    int t  = threadIdx.x;     // 0..255 == ci
    const float* wr = w + ((size_t)co * 256 + t) * 9;
    float s = 0.0f;
    #pragma unroll
    for (int k = 0; k < 9; ++k) {
        float wv = wr[k];
        s += fabsf(wv);
        g_wB[sub][((size_t)(k * 256 + co)) * 256 + t] = sgnb(wv);
    }
    __shared__ float red[256];
    red[t] = s;
    __syncthreads();
    for (int o = 128; o > 0; o >>= 1) {
        if (t < o) red[t] += red[t + o];
        __syncthreads();
    }
    if (t == 0) {
        float alpha = red[0] / 2304.0f;
        float inv = rsqrtf(v[co] + 1e-5f);
        float gi = g[co] * inv;
        g_s1[sub][co] = alpha * gi;
        g_s2[sub][co] = sc[co] * alpha * gi;
        g_c0[sub][co] = b[co] - m[co] * gi;
    }
}

// ---------------- binarize x (NCHW) into two NHWC bf16 sign streams ----------------
__global__ void binprep_kernel(const float* __restrict__ x,
                               const float* __restrict__ shA,
                               const float* __restrict__ shB) {
    __shared__ float tile[32][33];
    int n   = blockIdx.z;
    int hw0 = blockIdx.x * 32;
    int c0  = blockIdx.y * 32;
    int tx = threadIdx.x;   // 0..31
    int ty = threadIdx.y;   // 0..7
    #pragma unroll
    for (int k = 0; k < 4; ++k) {
        int cl = ty + k * 8;
        tile[cl][tx] = x[((size_t)(n * 256 + c0 + cl)) * HWSZ + hw0 + tx];
    }
    __syncthreads();
    int c = c0 + tx;
    float sA = shA[c], sB = shB[c];
    #pragma unroll
    for (int k = 0; k < 4; ++k) {
        int hwl = ty + k * 8;
        float vv = tile[tx][hwl];
        size_t o = ((size_t)(n * HWSZ + hw0 + hwl)) * 256 + c;
        g_ba1a[o] = sgnb(vv + sA);
        g_ba1b[o] = sgnb(vv + sB);
    }
}

// ---------------- fused dual-stream implicit-GEMM binary conv ----------------
// PASS 0: A = g_ba1a/b, res = x (NCHW), out = g_out1 (NCHW), emits g_ba2a/b
// PASS 1: A = g_ba2a/b, res = g_out1,   out = d_out (NCHW)
template<int PASS>
__global__ void __launch_bounds__(256, 1)
conv_kernel(const float* __restrict__ resX, float* __restrict__ outF,
            const float* __restrict__ shA, const float* __restrict__ shB) {
    extern __shared__ __align__(1024) char smem[];
    const uint32_t sb = (uint32_t)__cvta_generic_to_shared(smem);

    const __nv_bfloat16* __restrict__ baA = PASS ? g_ba2a : g_ba1a;
    const __nv_bfloat16* __restrict__ baB = PASS ? g_ba2b : g_ba1b;
    const __nv_bfloat16* __restrict__ wB  = g_wB[PASS];
    const float* __restrict__ res = PASS ? g_out1 : resX;
    float* __restrict__ outp = PASS ? outF : g_out1;

    const int t  = threadIdx.x;
    const int m0 = blockIdx.x * 128;
    const int n0 = blockIdx.y * 128;

    // ----- loader precompute: thread t loads 64B of one row per buffer -----
    const int lrow  = t >> 1;        // 0..127
    const int lhalf = t & 1;         // which 32-ci half
    const int p  = m0 + lrow;
    const int pn = p / HWSZ;
    const int phw = p - pn * HWSZ;
    const int ph = phw / 56;
    const int pw = phw - ph * 56;
    const uint32_t dA = lrow * 128 + lhalf * 64;   // byte offset within tile

    // ----- MMA fragment addressing precompute -----
    const int warp = t >> 5, lane = t & 31;
    const int wm = warp >> 1;                 // 0..3 (M group, 32 rows)
    const int wn = warp & 1;                  // 0..1 (N group, 64 cols)
    const int rowA = wm * 32 + (lane & 15);
    const int colA = (lane >> 4) * 16;        // bytes
    const int bg = lane >> 3, br = lane & 7;
    const int rowB = wn * 64 + (bg >> 1) * 8 + br;
    const int colB = (bg & 1) * 16;           // bytes

    float acc0[2][8][4], acc1[2][8][4];
    #pragma unroll
    for (int mi = 0; mi < 2; ++mi)
        #pragma unroll
        for (int ni = 0; ni < 8; ++ni)
            #pragma unroll
            for (int e = 0; e < 4; ++e) { acc0[mi][ni][e] = 0.0f; acc1[mi][ni][e] = 0.0f; }

    auto issue = [&](int s, int buf) {
        int tap = s >> 2;                 // 0..8
        int ci0 = (s & 3) << 6;           // 0/64/128/192
        int dh = tap / 3 - 1, dw = tap - (tap / 3) * 3 - 1;
        int hh = ph + dh, ww = pw + dw;
        bool valid = (hh >= 0) && (hh < 56) && (ww >= 0) && (ww < 56);
        size_t aoff = ((size_t)(pn * HWSZ + hh * 56 + ww) * 256 + ci0 + lhalf * 32) * 2;
        const char* a0 = valid ? (const char*)baA + aoff : (const char*)baA;
        const char* a1 = valid ? (const char*)baB + aoff : (const char*)baB;
        const char* bs = (const char*)wB +
            ((size_t)(tap * 256 + n0 + lrow) * 256 + ci0 + lhalf * 32) * 2;
        uint32_t dbase = sb + (uint32_t)buf * 49152;
        #pragma unroll
        for (int k = 0; k < 4; ++k) {
            cp16(dbase +          sw(dA + k * 16), a0 + k * 16, valid);
            cp16(dbase + 16384u + sw(dA + k * 16), a1 + k * 16, valid);
            cp16(dbase + 32768u + sw(dA + k * 16), bs + k * 16, true);
        }
        asm volatile("cp.async.commit_group;" ::: "memory");
    };

    issue(0, 0);

    #pragma unroll 1
    for (int s = 0; s < 36; ++s) {
        if (s + 1 < 36) {
            issue(s + 1, (s + 1) & 1);
            asm volatile("cp.async.wait_group 1;" ::: "memory");
        } else {
            asm volatile("cp.async.wait_group 0;" ::: "memory");
        }
        __syncthreads();

        const uint32_t A0b = sb + (uint32_t)(s & 1) * 49152;
        const uint32_t A1b = A0b + 16384u;
        const uint32_t Bb  = A0b + 32768u;

        #pragma unroll
        for (int kk = 0; kk < 4; ++kk) {
            uint32_t b[4][4];
            #pragma unroll
            for (int nf = 0; nf < 4; ++nf) {
                uint32_t off = (uint32_t)(rowB + nf * 16) * 128 + kk * 32 + colB;
                LDSM4(b[nf][0], b[nf][1], b[nf][2], b[nf][3], Bb + sw(off));
            }
            #pragma unroll
            for (int mi = 0; mi < 2; ++mi) {
                uint32_t off = (uint32_t)(rowA + mi * 16) * 128 + kk * 32 + colA;
                uint32_t a[4];
                LDSM4(a[0], a[1], a[2], a[3], A0b + sw(off));
                #pragma unroll
                for (int nf = 0; nf < 4; ++nf) {
                    MMA_OP(acc0[mi][nf * 2],     a, b[nf][0], b[nf][1]);
                    MMA_OP(acc0[mi][nf * 2 + 1], a, b[nf][2], b[nf][3]);
                }
                LDSM4(a[0], a[1], a[2], a[3], A1b + sw(off));
                #pragma unroll
                for (int nf = 0; nf < 4; ++nf) {
                    MMA_OP(acc1[mi][nf * 2],     a, b[nf][0], b[nf][1]);
                    MMA_OP(acc1[mi][nf * 2 + 1], a, b[nf][2], b[nf][3]);
                }
            }
        }
        __syncthreads();
    }

    // ----------- epilogue -----------
    float* stg = (float*)smem;   // [128 co][129]  (pad 1 float)

    // phase 1: regs -> smem (apply fused affine)
    #pragma unroll
    for (int mi = 0; mi < 2; ++mi)
        #pragma unroll
        for (int ni = 0; ni < 8; ++ni)
            #pragma unroll
            for (int e = 0; e < 4; ++e) {
                int r = wm * 32 + mi * 16 + (lane >> 2) + (e >> 1) * 8;
                int c = wn * 64 + ni * 8 + (lane & 3) * 2 + (e & 1);
                int cg = n0 + c;
                float vv = g_s1[PASS][cg] * acc0[mi][ni][e]
                         + g_s2[PASS][cg] * acc1[mi][ni][e]
                         + g_c0[PASS][cg];
                stg[c * 129 + r] = vv;
            }
    __syncthreads();

    // phase 2a: + residual, clamp, write NCHW coalesced (warp w owns co rows)
    #pragma unroll 1
    for (int it = 0; it < 16; ++it) {
        int c  = it * 8 + warp;
        int cg = n0 + c;
        int pl = lane * 4;
        int pp = m0 + pl;
        int nn = pp / HWSZ;
        int hw = pp - nn * HWSZ;
        size_t gaddr = ((size_t)(nn * 256 + cg)) * HWSZ + hw;
        float4 r4 = *(const float4*)(res + gaddr);
        float4 v4;
        v4.x = fminf(fmaxf(stg[c * 129 + pl + 0] + r4.x, -1.0f), 1.0f);
        v4.y = fminf(fmaxf(stg[c * 129 + pl + 1] + r4.y, -1.0f), 1.0f);
        v4.z = fminf(fmaxf(stg[c * 129 + pl + 2] + r4.z, -1.0f), 1.0f);
        v4.w = fminf(fmaxf(stg[c * 129 + pl + 3] + r4.w, -1.0f), 1.0f);
        *(float4*)(outp + gaddr) = v4;
        if (PASS == 0) {
            stg[c * 129 + pl + 0] = v4.x;
            stg[c * 129 + pl + 1] = v4.y;
            stg[c * 129 + pl + 2] = v4.z;
            stg[c * 129 + pl + 3] = v4.w;
        }
    }

    if (PASS == 0) {
        __syncthreads();
        // phase 2b: emit next sub-block's binarized NHWC streams (coalesced)
        #pragma unroll 1
        for (int it = 0; it < 16; ++it) {
            int pl = it * 8 + warp;
            size_t pg = (size_t)(m0 + pl) * 256 + n0;
            int c0i = lane * 4;
            __align__(8) __nv_bfloat16 ha[4], hb[4];
            #pragma unroll
            for (int k = 0; k < 4; ++k) {
                float vv = stg[(c0i + k) * 129 + pl];
                int cg = n0 + c0i + k;
                ha[k] = sgnb(vv + shA[cg]);
                hb[k] = sgnb(vv + shB[cg]);
            }
            *(uint2*)(g_ba2a + pg + c0i) = *(uint2*)ha;
            *(uint2*)(g_ba2b + pg + c0i) = *(uint2*)hb;
        }
    }
}

// ---------------- launch ----------------
extern "C" void kernel_launch(void* const* d_in, const int* in_sizes, int n_in,
                              void* d_out, int out_size) {
    const float* x    = (const float*)d_in[0];
    const float* sh11 = (const float*)d_in[1];
    const float* sh12 = (const float*)d_in[2];
    const float* w1   = (const float*)d_in[3];
    const float* sc1  = (const float*)d_in[4];
    const float* g1   = (const float*)d_in[5];
    const float* b1   = (const float*)d_in[6];
    const float* m1   = (const float*)d_in[7];
    const float* v1   = (const float*)d_in[8];
    const float* sh21 = (const float*)d_in[9];
    const float* sh22 = (const float*)d_in[10];
    const float* w2   = (const float*)d_in[11];
    const float* sc2  = (const float*)d_in[12];
    const float* g2   = (const float*)d_in[13];
    const float* b2   = (const float*)d_in[14];
    const float* m2   = (const float*)d_in[15];
    const float* v2   = (const float*)d_in[16];
    float* out = (float*)d_out;

    cudaFuncSetAttribute(conv_kernel<0>,
                         cudaFuncAttributeMaxDynamicSharedMemorySize, 98304);
    cudaFuncSetAttribute(conv_kernel<1>,
                         cudaFuncAttributeMaxDynamicSharedMemorySize, 98304);

    wprep_kernel<<<256, 256>>>(0, w1, sc1, g1, b1, m1, v1);
    wprep_kernel<<<256, 256>>>(1, w2, sc2, g2, b2, m2, v2);
    binprep_kernel<<<dim3(98, 8, 32), dim3(32, 8)>>>(x, sh11, sh12);
    conv_kernel<0><<<dim3(784, 2), 256, 98304>>>(x, nullptr, sh21, sh22);
    conv_kernel<1><<<dim3(784, 2), 256, 98304>>>(nullptr, out, sh21, sh22);
}

// round 7
// speedup vs baseline: 1.2979x; 1.2979x over previous
#include <cuda_runtime.h>
#include <cuda_bf16.h>
#include <cstdint>
#include <cstddef>

// ---------------- problem constants ----------------
#define HWSZ 3136          // 56*56
#define NPIX 100352        // 32*3136

// ---------------- scratch (device globals; no runtime alloc) ----------------
__device__ __align__(256) __nv_bfloat16 g_ba1a[(size_t)NPIX * 256];
__device__ __align__(256) __nv_bfloat16 g_ba1b[(size_t)NPIX * 256];
__device__ __align__(256) __nv_bfloat16 g_ba2a[(size_t)NPIX * 256];
__device__ __align__(256) __nv_bfloat16 g_ba2b[(size_t)NPIX * 256];
__device__ __align__(256) float         g_out1[(size_t)NPIX * 256];   // NCHW
__device__ __align__(256) __nv_bfloat16 g_wB[2][9 * 256 * 256];       // [tap][co][ci] signs
__device__ float g_s1[2][256];
__device__ float g_s2[2][256];
__device__ float g_c0[2][256];

// ---------------- helpers ----------------
__device__ __forceinline__ __nv_bfloat16 sgnb(float v) {
    float s = (v > 0.0f) ? 1.0f : ((v < 0.0f) ? -1.0f : 0.0f);
    return __float2bfloat16(s);
}

__device__ __forceinline__ uint32_t sw(uint32_t o) {   // SW128 swizzle
    return o ^ ((o >> 3) & 0x70);
}

__device__ __forceinline__ void cp16(uint32_t dst, const void* src, bool pred) {
    int sz = pred ? 16 : 0;
    asm volatile("cp.async.cg.shared.global [%0], [%1], 16, %2;"
                 :: "r"(dst), "l"(src), "r"(sz));
}

#define LDSM4(R0,R1,R2,R3,ADDR) \
    asm volatile("ldmatrix.sync.aligned.m8n8.x4.shared.b16 {%0,%1,%2,%3}, [%4];" \
        : "=r"(R0),"=r"(R1),"=r"(R2),"=r"(R3) : "r"(ADDR))

#define MMA_OP(D, A, B0, B1) \
    asm volatile("mma.sync.aligned.m16n8k16.row.col.f32.bf16.bf16.f32 " \
        "{%0,%1,%2,%3}, {%4,%5,%6,%7}, {%8,%9}, {%0,%1,%2,%3};" \
        : "+f"((D)[0]), "+f"((D)[1]), "+f"((D)[2]), "+f"((D)[3]) \
        : "r"((A)[0]), "r"((A)[1]), "r"((A)[2]), "r"((A)[3]), "r"(B0), "r"(B1))

// ---------------- weight prep: alpha, sign weights, folded BN constants ----------------
__global__ void wprep_kernel(int sub,
                             const float* __restrict__ w,
                             const float* __restrict__ sc,
                             const float* __restrict__ g,
                             const float* __restrict__ b,
                             const float* __restrict__ m,
                             const float* __restrict__ v) {
    int co = blockIdx.x;      // 0..255
    int t  = threadIdx.x;     // 0..255 == ci
    const float* wr = w + ((size_t)co * 256 + t) * 9;
    float s = 0.0f;
    #pragma unroll
    for (int k = 0; k < 9; ++k) {
        float wv = wr[k];
        s += fabsf(wv);
        g_wB[sub][((size_t)(k * 256 + co)) * 256 + t] = sgnb(wv);
    }
    __shared__ float red[256];
    red[t] = s;
    __syncthreads();
    for (int o = 128; o > 0; o >>= 1) {
        if (t < o) red[t] += red[t + o];
        __syncthreads();
    }
    if (t == 0) {
        float alpha = red[0] / 2304.0f;
        float inv = rsqrtf(v[co] + 1e-5f);
        float gi = g[co] * inv;
        g_s1[sub][co] = alpha * gi;
        g_s2[sub][co] = sc[co] * alpha * gi;
        g_c0[sub][co] = b[co] - m[co] * gi;
    }
}

// ---------------- binarize x (NCHW) into two NHWC bf16 sign streams ----------------
__global__ void binprep_kernel(const float* __restrict__ x,
                               const float* __restrict__ shA,
                               const float* __restrict__ shB) {
    __shared__ float tile[32][33];
    int n   = blockIdx.z;
    int hw0 = blockIdx.x * 32;
    int c0  = blockIdx.y * 32;
    int tx = threadIdx.x;   // 0..31
    int ty = threadIdx.y;   // 0..7
    #pragma unroll
    for (int k = 0; k < 4; ++k) {
        int cl = ty + k * 8;
        tile[cl][tx] = x[((size_t)(n * 256 + c0 + cl)) * HWSZ + hw0 + tx];
    }
    __syncthreads();
    int c = c0 + tx;
    float sA = shA[c], sB = shB[c];
    #pragma unroll
    for (int k = 0; k < 4; ++k) {
        int hwl = ty + k * 8;
        float vv = tile[tx][hwl];
        size_t o = ((size_t)(n * HWSZ + hw0 + hwl)) * 256 + c;
        g_ba1a[o] = sgnb(vv + sA);
        g_ba1b[o] = sgnb(vv + sB);
    }
}

// ---------------- fused dual-stream implicit-GEMM binary conv ----------------
// BM=128 pix, BN=128 co, BK=64 ci, 512 threads (4x4 warps, warp tile 32x32),
// 3-stage cp.async pipeline, 1 barrier per K-stage.
// PASS 0: A = g_ba1a/b, res = x (NCHW), out = g_out1 (NCHW), emits g_ba2a/b
// PASS 1: A = g_ba2a/b, res = g_out1,   out = d_out (NCHW)
template<int PASS>
__global__ void __launch_bounds__(512, 1)
conv_kernel(const float* __restrict__ resX, float* __restrict__ outF,
            const float* __restrict__ shA, const float* __restrict__ shB) {
    extern __shared__ __align__(1024) char smem[];
    const uint32_t sb = (uint32_t)__cvta_generic_to_shared(smem);

    const __nv_bfloat16* __restrict__ baA = PASS ? g_ba2a : g_ba1a;
    const __nv_bfloat16* __restrict__ baB = PASS ? g_ba2b : g_ba1b;
    const __nv_bfloat16* __restrict__ wB  = g_wB[PASS];
    const float* __restrict__ res = PASS ? g_out1 : resX;
    float* __restrict__ outp = PASS ? outF : g_out1;

    const int t  = threadIdx.x;
    const int m0 = blockIdx.x * 128;
    const int n0 = blockIdx.y * 128;

    // ----- loader precompute: thread t loads 32B (2x16B) of one row per tile -----
    const int lrow = t >> 2;          // 0..127
    const int lq   = t & 3;           // which 16-ci quarter
    const int p  = m0 + lrow;
    const int pn = p / HWSZ;
    const int phw = p - pn * HWSZ;
    const int ph = phw / 56;
    const int pw = phw - ph * 56;
    const uint32_t dA = (uint32_t)lrow * 128 + (uint32_t)lq * 32;  // byte off in tile

    // ----- MMA fragment addressing precompute (4x4 warp grid, 32x32 warp tile) -----
    const int warp = t >> 5, lane = t & 31;
    const int wm = warp & 3;                  // M group (32 rows)
    const int wn = warp >> 2;                 // N group (32 cols)
    const int rowA = wm * 32 + (lane & 15);
    const int colA = (lane >> 4) * 16;        // bytes
    const int bg = lane >> 3, br = lane & 7;
    const int rowB = wn * 32 + (bg >> 1) * 8 + br;
    const int colB = (bg & 1) * 16;           // bytes

    float acc0[2][4][4], acc1[2][4][4];
    #pragma unroll
    for (int mi = 0; mi < 2; ++mi)
        #pragma unroll
        for (int ni = 0; ni < 4; ++ni)
            #pragma unroll
            for (int e = 0; e < 4; ++e) { acc0[mi][ni][e] = 0.0f; acc1[mi][ni][e] = 0.0f; }

    auto issue = [&](int s, int buf) {
        int tap = s >> 2;                 // 0..8
        int ci0 = (s & 3) << 6;           // 0/64/128/192
        int dh = tap / 3 - 1, dw = tap - (tap / 3) * 3 - 1;
        int hh = ph + dh, ww = pw + dw;
        bool valid = (hh >= 0) && (hh < 56) && (ww >= 0) && (ww < 56);
        size_t aoff = ((size_t)(pn * HWSZ + hh * 56 + ww) * 256 + ci0 + lq * 16) * 2;
        const char* a0 = valid ? (const char*)baA + aoff : (const char*)baA;
        const char* a1 = valid ? (const char*)baB + aoff : (const char*)baB;
        const char* bs = (const char*)wB +
            ((size_t)(tap * 256 + n0 + lrow) * 256 + ci0 + lq * 16) * 2;
        uint32_t dbase = sb + (uint32_t)buf * 49152u;
        cp16(dbase +          sw(dA),      a0,      valid);
        cp16(dbase +          sw(dA + 16), a0 + 16, valid);
        cp16(dbase + 16384u + sw(dA),      a1,      valid);
        cp16(dbase + 16384u + sw(dA + 16), a1 + 16, valid);
        cp16(dbase + 32768u + sw(dA),      bs,      true);
        cp16(dbase + 32768u + sw(dA + 16), bs + 16, true);
        asm volatile("cp.async.commit_group;" ::: "memory");
    };

    issue(0, 0);
    issue(1, 1);

    int buf = 0, nbuf = 2;
    #pragma unroll 1
    for (int s = 0; s < 36; ++s) {
        if (s + 1 < 36) {
            asm volatile("cp.async.wait_group 1;" ::: "memory");
        } else {
            asm volatile("cp.async.wait_group 0;" ::: "memory");
        }
        __syncthreads();
        if (s + 2 < 36) {
            issue(s + 2, nbuf);
        }

        const uint32_t A0b = sb + (uint32_t)buf * 49152u;
        const uint32_t A1b = A0b + 16384u;
        const uint32_t Bb  = A0b + 32768u;

        #pragma unroll
        for (int kk = 0; kk < 4; ++kk) {
            uint32_t b[2][4];
            #pragma unroll
            for (int nf = 0; nf < 2; ++nf) {
                uint32_t off = (uint32_t)(rowB + nf * 16) * 128 + kk * 32 + colB;
                LDSM4(b[nf][0], b[nf][1], b[nf][2], b[nf][3], Bb + sw(off));
            }
            #pragma unroll
            for (int mi = 0; mi < 2; ++mi) {
                uint32_t off = (uint32_t)(rowA + mi * 16) * 128 + kk * 32 + colA;
                uint32_t a[4];
                LDSM4(a[0], a[1], a[2], a[3], A0b + sw(off));
                #pragma unroll
                for (int nf = 0; nf < 2; ++nf) {
                    MMA_OP(acc0[mi][nf * 2],     a, b[nf][0], b[nf][1]);
                    MMA_OP(acc0[mi][nf * 2 + 1], a, b[nf][2], b[nf][3]);
                }
                LDSM4(a[0], a[1], a[2], a[3], A1b + sw(off));
                #pragma unroll
                for (int nf = 0; nf < 2; ++nf) {
                    MMA_OP(acc1[mi][nf * 2],     a, b[nf][0], b[nf][1]);
                    MMA_OP(acc1[mi][nf * 2 + 1], a, b[nf][2], b[nf][3]);
                }
            }
        }

        buf = (buf == 2) ? 0 : buf + 1;
        nbuf = (nbuf == 2) ? 0 : nbuf + 1;
    }
    __syncthreads();

    // ----------- epilogue -----------
    float* stg = (float*)smem;   // [128 co][129]  (pad 1 float)

    // phase 1: regs -> smem (apply fused affine)
    #pragma unroll
    for (int mi = 0; mi < 2; ++mi)
        #pragma unroll
        for (int ni = 0; ni < 4; ++ni)
            #pragma unroll
            for (int e = 0; e < 4; ++e) {
                int r = wm * 32 + mi * 16 + (lane >> 2) + (e >> 1) * 8;
                int c = wn * 32 + ni * 8 + (lane & 3) * 2 + (e & 1);
                int cg = n0 + c;
                float vv = g_s1[PASS][cg] * acc0[mi][ni][e]
                         + g_s2[PASS][cg] * acc1[mi][ni][e]
                         + g_c0[PASS][cg];
                stg[c * 129 + r] = vv;
            }
    __syncthreads();

    // phase 2a: + residual, clamp, write NCHW coalesced (warp owns co rows)
    #pragma unroll 1
    for (int it = 0; it < 8; ++it) {
        int c  = it * 16 + warp;
        int cg = n0 + c;
        int pl = lane * 4;
        int pp = m0 + pl;
        int nn = pp / HWSZ;
        int hw = pp - nn * HWSZ;
        size_t gaddr = ((size_t)(nn * 256 + cg)) * HWSZ + hw;
        float4 r4 = *(const float4*)(res + gaddr);
        float4 v4;
        v4.x = fminf(fmaxf(stg[c * 129 + pl + 0] + r4.x, -1.0f), 1.0f);
        v4.y = fminf(fmaxf(stg[c * 129 + pl + 1] + r4.y, -1.0f), 1.0f);
        v4.z = fminf(fmaxf(stg[c * 129 + pl + 2] + r4.z, -1.0f), 1.0f);
        v4.w = fminf(fmaxf(stg[c * 129 + pl + 3] + r4.w, -1.0f), 1.0f);
        *(float4*)(outp + gaddr) = v4;
        if (PASS == 0) {
            stg[c * 129 + pl + 0] = v4.x;
            stg[c * 129 + pl + 1] = v4.y;
            stg[c * 129 + pl + 2] = v4.z;
            stg[c * 129 + pl + 3] = v4.w;
        }
    }

    if (PASS == 0) {
        __syncthreads();
        // phase 2b: emit next sub-block's binarized NHWC streams (coalesced)
        #pragma unroll 1
        for (int it = 0; it < 8; ++it) {
            int pl = it * 16 + warp;
            size_t pg = (size_t)(m0 + pl) * 256 + n0;
            int c0i = lane * 4;
            __align__(8) __nv_bfloat16 ha[4], hb[4];
            #pragma unroll
            for (int k = 0; k < 4; ++k) {
                float vv = stg[(c0i + k) * 129 + pl];
                int cg = n0 + c0i + k;
                ha[k] = sgnb(vv + shA[cg]);
                hb[k] = sgnb(vv + shB[cg]);
            }
            *(uint2*)(g_ba2a + pg + c0i) = *(uint2*)ha;
            *(uint2*)(g_ba2b + pg + c0i) = *(uint2*)hb;
        }
    }
}

// ---------------- launch ----------------
extern "C" void kernel_launch(void* const* d_in, const int* in_sizes, int n_in,
                              void* d_out, int out_size) {
    const float* x    = (const float*)d_in[0];
    const float* sh11 = (const float*)d_in[1];
    const float* sh12 = (const float*)d_in[2];
    const float* w1   = (const float*)d_in[3];
    const float* sc1  = (const float*)d_in[4];
    const float* g1   = (const float*)d_in[5];
    const float* b1   = (const float*)d_in[6];
    const float* m1   = (const float*)d_in[7];
    const float* v1   = (const float*)d_in[8];
    const float* sh21 = (const float*)d_in[9];
    const float* sh22 = (const float*)d_in[10];
    const float* w2   = (const float*)d_in[11];
    const float* sc2  = (const float*)d_in[12];
    const float* g2   = (const float*)d_in[13];
    const float* b2   = (const float*)d_in[14];
    const float* m2   = (const float*)d_in[15];
    const float* v2   = (const float*)d_in[16];
    float* out = (float*)d_out;

    cudaFuncSetAttribute(conv_kernel<0>,
                         cudaFuncAttributeMaxDynamicSharedMemorySize, 147456);
    cudaFuncSetAttribute(conv_kernel<1>,
                         cudaFuncAttributeMaxDynamicSharedMemorySize, 147456);

    wprep_kernel<<<256, 256>>>(0, w1, sc1, g1, b1, m1, v1);
    wprep_kernel<<<256, 256>>>(1, w2, sc2, g2, b2, m2, v2);
    binprep_kernel<<<dim3(98, 8, 32), dim3(32, 8)>>>(x, sh11, sh12);
    conv_kernel<0><<<dim3(784, 2), 512, 147456>>>(x, nullptr, sh21, sh22);
    conv_kernel<1><<<dim3(784, 2), 512, 147456>>>(nullptr, out, sh21, sh22);
}